// round 16
// baseline (speedup 1.0000x reference)
#include <cuda_runtime.h>
#include <cuda_bf16.h>
#include <cstdint>

#define NT 16384   // x rows
#define MS 4096    // sonata rows
#define NB 8       // batches
#define NH 8       // heads
#define DH 64      // head dim
#define NG 64      // slice groups
#define DM 512     // model dim
#define SCL 0.125f // D^-0.5

#define SW64_(o) ((o) ^ (((o) >> 3) & 0x30))

__device__ __forceinline__ uint32_t smem_to_u32(const void* p) {
    uint32_t a;
    asm("{ .reg .u64 tmp; cvta.to.shared.u64 tmp, %1; cvt.u32.u64 %0, tmp; }"
        : "=r"(a) : "l"(p));
    return a;
}
__device__ __forceinline__ void ldsm4(uint32_t a[4], uint32_t addr) {
    asm volatile("ldmatrix.sync.aligned.m8n8.x4.shared.b16 {%0,%1,%2,%3}, [%4];"
                 : "=r"(a[0]), "=r"(a[1]), "=r"(a[2]), "=r"(a[3]) : "r"(addr));
}
__device__ __forceinline__ void mma16816(float c[4], const uint32_t a[4],
                                         uint32_t b0, uint32_t b1) {
    asm volatile(
        "mma.sync.aligned.m16n8k16.row.col.f32.bf16.bf16.f32 "
        "{%0,%1,%2,%3}, {%4,%5,%6,%7}, {%8,%9}, {%0,%1,%2,%3};"
        : "+f"(c[0]), "+f"(c[1]), "+f"(c[2]), "+f"(c[3])
        : "r"(a[0]), "r"(a[1]), "r"(a[2]), "r"(a[3]), "r"(b0), "r"(b1));
}
__device__ __forceinline__ void cp16(uint32_t dst, const void* src) {
    asm volatile("cp.async.cg.shared.global [%0], [%1], 16;" :: "r"(dst), "l"(src));
}
#define CP_COMMIT() asm volatile("cp.async.commit_group;" ::: "memory")
#define CP_WAIT2() asm volatile("cp.async.wait_group 2;" ::: "memory")
#define CP_WAIT1() asm volatile("cp.async.wait_group 1;" ::: "memory")
#define CP_WAIT0() asm volatile("cp.async.wait_group 0;" ::: "memory")

__device__ __forceinline__ void bsplit(float v, __nv_bfloat16& h, __nv_bfloat16& l) {
    h = __float2bfloat16(v);
    l = __float2bfloat16(v - __bfloat162float(h));
}

// pipelined MMA smem: 3 stages x (AH 8K | AL 8K | BH 8K | BL 8K) = 96KB
#define STG_BYTES 32768
#define OFFS_AH 0
#define OFFS_AL 8192
#define OFFS_BH 16384
#define OFFS_BL 24576
#define SMEM_MMA (3 * STG_BYTES)
#define KSLAB 32
#define NSLAB (DM / KSLAB)

// fused qkv+attn smem: a[64][65] + 3x W[64][64] + q,k,v[64][64] + s[64][64]
#define QKV_SMEM ((64 * 65 + 3 * 4096 + 3 * 4096 + 4096) * 4)

// ---------------- device scratch ----------------
__device__ float g_bcomb[DM];
__device__ float g_fx[(size_t)NT * DM];
__device__ __nv_bfloat16 g_xhi[(size_t)NT * DM], g_xlo[(size_t)NT * DM];
__device__ __nv_bfloat16 g_Bthi[(size_t)2 * DM * DM], g_Btlo[(size_t)2 * DM * DM]; // [1024][512]
__device__ __nv_bfloat16 g_whi[(size_t)NT * DM], g_wlo[(size_t)NT * DM];
__device__ __nv_bfloat16 g_Pthi[(size_t)NB * DM * DM], g_Ptlo[(size_t)NB * DM * DM]; // [b][c][k]
__device__ float g_tokens[NB * NH * NG * DH];
__device__ float g_norms[NB * NH * NG];
__device__ float g_outtok[NB * NH * NG * DH];
__device__ float g_ks[(size_t)MS * DM];
__device__ float g_vs[(size_t)MS * DM];
__device__ float g_scores[(size_t)NB * NH * NG * MS];
__device__ float2 g_pstat[NB * NH * 8 * NG];    // per-(bh,slice,g) partial (m, s)
__device__ int g_rowlist[NT], g_rowcnt[NB], g_rowstart[NB + 1], g_rowcur[NB];
__device__ int g_mlist[MS], g_mcnt[NB], g_mstart[NB + 1], g_mcur[NB];

// ---------------- setup kernels ----------------
__global__ void k_zero() {
    int i = blockIdx.x * 256 + threadIdx.x;
    if (i < NB * NH * NG * DH) g_tokens[i] = 0.f;
    if (i < NB * NH * NG) g_norms[i] = 0.f;
    if (i < NB) {
        g_rowcnt[i] = 0; g_mcnt[i] = 0;
        g_rowcur[i] = 0; g_mcur[i] = 0;
    }
}

__global__ void k_bcomb(const float* __restrict__ bx, const float* __restrict__ Wsl,
                        const float* __restrict__ bsl) {
    int o = threadIdx.x;  // 512
    int h = o >> 6, g = o & 63;
    float acc = bsl[g];
    for (int d = 0; d < 64; d++) acc = fmaf(bx[h * 64 + d], Wsl[d * 64 + g], acc);
    g_bcomb[o] = acc;
}

// x fp32 -> bf16 hi/lo split
__global__ void k_cvt_x(const float* __restrict__ x) {
    size_t i = (size_t)blockIdx.x * 256 + threadIdx.x;  // one float4 each
    float4 v = ((const float4*)x)[i];
    __nv_bfloat16 h0, h1, h2, h3, l0, l1, l2, l3;
    bsplit(v.x, h0, l0); bsplit(v.y, h1, l1);
    bsplit(v.z, h2, l2); bsplit(v.w, h3, l3);
    ((__nv_bfloat162*)g_xhi)[i * 2 + 0] = __halves2bfloat162(h0, h1);
    ((__nv_bfloat162*)g_xhi)[i * 2 + 1] = __halves2bfloat162(h2, h3);
    ((__nv_bfloat162*)g_xlo)[i * 2 + 0] = __halves2bfloat162(l0, l1);
    ((__nv_bfloat162*)g_xlo)[i * 2 + 1] = __halves2bfloat162(l2, l3);
}

// y==1: Bt rows 0..511 (transposed Wfx); y==0: Bt rows 512..1023 from Wcomb = Wx·Wsl
__global__ void k_wcomb(const float* __restrict__ Wx, const float* __restrict__ Wsl,
                        const float* __restrict__ Wfx) {
    int c = blockIdx.x;  // 0..511
    int t = threadIdx.x;
    if (blockIdx.y == 1) {
        for (int k = t; k < DM; k += 256) {
            __nv_bfloat16 h, l;
            bsplit(Wfx[(size_t)k * DM + c], h, l);
            g_Bthi[(size_t)c * DM + k] = h;
            g_Btlo[(size_t)c * DM + k] = l;
        }
        return;
    }
    __shared__ float s_sl[4096];
    for (int i = t; i < 4096; i += 256) s_sl[i] = Wsl[i];
    __syncthreads();
    for (int o = t; o < 512; o += 256) {
        int h = o >> 6, g = o & 63;
        const float* wxr = Wx + (size_t)c * DM + h * 64;
        float acc = 0.f;
        for (int d = 0; d < 64; d++) acc = fmaf(wxr[d], s_sl[d * 64 + g], acc);
        __nv_bfloat16 hh, ll;
        bsplit(acc, hh, ll);
        g_Bthi[(size_t)(DM + o) * DM + c] = hh;
        g_Btlo[(size_t)(DM + o) * DM + c] = ll;
    }
}

__global__ void k_count(const int* __restrict__ bi, const int* __restrict__ sbi) {
    int i = blockIdx.x * 256 + threadIdx.x;
    if (i < NT) atomicAdd(&g_rowcnt[bi[i]], 1);
    else if (i < NT + MS) atomicAdd(&g_mcnt[sbi[i - NT]], 1);
}

__global__ void k_prefix() {
    if (threadIdx.x == 0) {
        int s = 0;
        for (int b = 0; b < NB; b++) { g_rowstart[b] = s; s += g_rowcnt[b]; }
        g_rowstart[NB] = s;
        s = 0;
        for (int b = 0; b < NB; b++) { g_mstart[b] = s; s += g_mcnt[b]; }
        g_mstart[NB] = s;
    }
}

__global__ void k_scatter(const int* __restrict__ bi, const int* __restrict__ sbi) {
    int i = blockIdx.x * 256 + threadIdx.x;
    if (i < NT) {
        int b = bi[i];
        int p = atomicAdd(&g_rowcur[b], 1);
        g_rowlist[g_rowstart[b] + p] = i;
    } else if (i < NT + MS) {
        int j = i - NT;
        int b = sbi[j];
        int p = atomicAdd(&g_mcur[b], 1);
        g_mlist[g_mstart[b] + p] = j;
    }
}

// ---------------- front GEMM via mma.sync bf16x3, 3-stage pipeline, fused slice-softmax ----------------
__global__ void __launch_bounds__(256, 2)
k_gemm_mma(const float* __restrict__ bfx, const float* __restrict__ temp) {
    extern __shared__ char dynsmem[];
    uint32_t sb = smem_to_u32(dynsmem);
    int t = threadIdx.x;
    int lane = t & 31, wid = t >> 5;
    int wm = (wid & 3) * 32, wn = (wid >> 2) * 64;
    int row0 = blockIdx.y * 128, col0 = blockIdx.x * 128;
    float acc[2][8][4] = {};
    int a_row = wm + (lane & 15);
    int a_u = lane >> 4;
    int b_row = wn + (lane & 7) + ((lane >> 4) << 3);
    int b_u = (lane >> 3) & 1;

    auto load_slab = [&](int kc, int stg) {
        uint32_t sbase = sb + stg * STG_BYTES;
#pragma unroll
        for (int half = 0; half < 2; half++) {
            int idx = half * 256 + t;
            int r = idx >> 2, c = idx & 3;
            uint32_t o = SW64_((uint32_t)(r * 64 + c * 16));
            size_t offa = (size_t)(row0 + r) * DM + kc + c * 8;
            size_t offb = (size_t)(col0 + r) * DM + kc + c * 8;
            cp16(sbase + OFFS_AH + o, g_xhi + offa);
            cp16(sbase + OFFS_AL + o, g_xlo + offa);
            cp16(sbase + OFFS_BH + o, g_Bthi + offb);
            cp16(sbase + OFFS_BL + o, g_Btlo + offb);
        }
        CP_COMMIT();
    };

    load_slab(0, 0);
    load_slab(KSLAB, 1);
#pragma unroll 1
    for (int ch = 0; ch < NSLAB; ch++) {
        if (ch + 2 < NSLAB) { load_slab((ch + 2) * KSLAB, (ch + 2) % 3); CP_WAIT2(); }
        else if (ch + 1 < NSLAB) { CP_WAIT1(); }
        else { CP_WAIT0(); }
        __syncthreads();
        uint32_t sbase = sb + (ch % 3) * STG_BYTES;
#pragma unroll
        for (int ks = 0; ks < 2; ks++) {
            uint32_t ah[2][4], al[2][4];
#pragma unroll
            for (int mt = 0; mt < 2; mt++) {
                uint32_t off = SW64_((uint32_t)((a_row + mt * 16) * 64 + ks * 32 + a_u * 16));
                ldsm4(ah[mt], sbase + OFFS_AH + off);
                ldsm4(al[mt], sbase + OFFS_AL + off);
            }
#pragma unroll
            for (int np = 0; np < 4; np++) {
                uint32_t bh[4], bl[4];
                uint32_t boff = SW64_((uint32_t)((b_row + np * 16) * 64 + ks * 32 + b_u * 16));
                ldsm4(bh, sbase + OFFS_BH + boff);
                ldsm4(bl, sbase + OFFS_BL + boff);
#pragma unroll
                for (int mt = 0; mt < 2; mt++) {
                    mma16816(acc[mt][np * 2 + 0], ah[mt], bh[0], bh[1]);
                    mma16816(acc[mt][np * 2 + 0], ah[mt], bl[0], bl[1]);
                    mma16816(acc[mt][np * 2 + 0], al[mt], bh[0], bh[1]);
                    mma16816(acc[mt][np * 2 + 1], ah[mt], bh[2], bh[3]);
                    mma16816(acc[mt][np * 2 + 1], ah[mt], bl[2], bl[3]);
                    mma16816(acc[mt][np * 2 + 1], al[mt], bh[2], bh[3]);
                }
            }
        }
        __syncthreads();
    }
    int g = lane >> 2, tig = lane & 3;
    bool isfx = (col0 < DM);
    if (isfx) {
#pragma unroll
        for (int mt = 0; mt < 2; mt++)
#pragma unroll
            for (int nt = 0; nt < 8; nt++) {
                int r1 = row0 + wm + mt * 16 + g;
                int c = col0 + wn + nt * 8 + tig * 2;
                float b0v = bfx[c], b1v = bfx[c + 1];
                *(float2*)(g_fx + (size_t)r1 * DM + c) =
                    make_float2(acc[mt][nt][0] + b0v, acc[mt][nt][1] + b1v);
                *(float2*)(g_fx + (size_t)(r1 + 8) * DM + c) =
                    make_float2(acc[mt][nt][2] + b0v, acc[mt][nt][3] + b1v);
            }
    } else {
        // fused slice softmax; w stored only as bf16 hi/lo split
        int cbase = col0 - DM;
        int h = (cbase + wn) >> 6;
        float it = 1.f / temp[h];
#pragma unroll
        for (int mt = 0; mt < 2; mt++)
#pragma unroll
            for (int half = 0; half < 2; half++) {
                int r1 = row0 + wm + mt * 16 + g + half * 8;
                float v[16];
#pragma unroll
                for (int nt = 0; nt < 8; nt++) {
                    int c = cbase + wn + nt * 8 + tig * 2;
                    v[nt * 2 + 0] = (acc[mt][nt][half * 2 + 0] + g_bcomb[c]) * it;
                    v[nt * 2 + 1] = (acc[mt][nt][half * 2 + 1] + g_bcomb[c + 1]) * it;
                }
                float m = v[0];
#pragma unroll
                for (int i = 1; i < 16; i++) m = fmaxf(m, v[i]);
                m = fmaxf(m, __shfl_xor_sync(0xFFFFFFFFu, m, 1));
                m = fmaxf(m, __shfl_xor_sync(0xFFFFFFFFu, m, 2));
                float s = 0.f;
#pragma unroll
                for (int i = 0; i < 16; i++) { v[i] = __expf(v[i] - m); s += v[i]; }
                s += __shfl_xor_sync(0xFFFFFFFFu, s, 1);
                s += __shfl_xor_sync(0xFFFFFFFFu, s, 2);
                float inv = 1.f / s;
#pragma unroll
                for (int nt = 0; nt < 8; nt++) {
                    int cw = cbase + wn + nt * 8 + tig * 2;
                    float w0 = v[nt * 2 + 0] * inv, w1 = v[nt * 2 + 1] * inv;
                    __nv_bfloat16 h0, l0, h1, l1;
                    bsplit(w0, h0, l0); bsplit(w1, h1, l1);
                    *(__nv_bfloat162*)(g_whi + (size_t)r1 * DM + cw) = __halves2bfloat162(h0, h1);
                    *(__nv_bfloat162*)(g_wlo + (size_t)r1 * DM + cw) = __halves2bfloat162(l0, l1);
                }
            }
    }
}

// tokens[b,h,g,d] = sum_{n in b} w[n,h,g] * fx[n,h,d]; norms[b,h,g] = sum w
// grid (64 bh, 32 row-slices); double-buffered cp.async gather of 32-row chunks
__global__ void k_tokens() {
    int bh = blockIdx.x;
    int b = bh >> 3, h = bh & 7;
    int cnt = g_rowcnt[b], start = g_rowstart[b];
    int c0 = (int)(((long long)cnt * blockIdx.y) >> 5);
    int c1 = (int)(((long long)cnt * (blockIdx.y + 1)) >> 5);
    if (c0 >= c1) return;
    int t = threadIdx.x;
    int tg = (t >> 4) * 4, td = (t & 15) * 4;
    float acc[4][4] = {};
    float nacc[4] = {};
    __shared__ int rid[2][32];
    __shared__ __nv_bfloat16 s_wh[2][32][64], s_wl[2][32][64];
    __shared__ float s_f[2][32][64];
    uint32_t a_wh = smem_to_u32(s_wh);
    uint32_t a_wl = smem_to_u32(s_wl);
    uint32_t a_f = smem_to_u32(s_f);
    int nch = (c1 - c0 + 31) >> 5;

    auto issue_data = [&](int ch, int buf) {
        int base = c0 + ch * 32;
        int nr = c1 - base; if (nr > 32) nr = 32;
        for (int u = t; u < nr * 32; u += 256) {
            int r = u >> 5, q = u & 31;
            size_t off = (size_t)rid[buf][r] * DM + h * 64;
            if (q < 16)
                cp16(a_f + (uint32_t)(buf * 2048 + r * 64) * 4 + q * 16, g_fx + off + q * 4);
            else if (q < 24)
                cp16(a_wh + (uint32_t)(buf * 2048 + r * 64) * 2 + (q - 16) * 16, g_whi + off + (q - 16) * 8);
            else
                cp16(a_wl + (uint32_t)(buf * 2048 + r * 64) * 2 + (q - 24) * 16, g_wlo + off + (q - 24) * 8);
        }
        CP_COMMIT();
    };

    if (t < 32) {
        int r = c0 + t;
        rid[0][t] = g_rowlist[start + (r < c1 ? r : c1 - 1)];
    }
    __syncthreads();
    issue_data(0, 0);
    int ridreg = 0;
    if (nch > 1 && t < 32) {
        int r = c0 + 32 + t;
        ridreg = g_rowlist[start + (r < c1 ? r : c1 - 1)];
    }
#pragma unroll 1
    for (int ch = 0; ch < nch; ch++) {
        int buf = ch & 1;
        if (ch + 1 < nch) {
            if (t < 32) rid[buf ^ 1][t] = ridreg;
            __syncthreads();
            issue_data(ch + 1, buf ^ 1);
            if (ch + 2 < nch && t < 32) {
                int r = c0 + (ch + 2) * 32 + t;
                ridreg = g_rowlist[start + (r < c1 ? r : c1 - 1)];
            }
            CP_WAIT1();
        } else {
            CP_WAIT0();
        }
        __syncthreads();
        int base = c0 + ch * 32;
        int nr = c1 - base; if (nr > 32) nr = 32;
        for (int r = 0; r < nr; r++) {
            float wv[4], fv[4];
#pragma unroll
            for (int i = 0; i < 4; i++) {
                wv[i] = __bfloat162float(s_wh[buf][r][tg + i]) + __bfloat162float(s_wl[buf][r][tg + i]);
                fv[i] = s_f[buf][r][td + i];
            }
#pragma unroll
            for (int i = 0; i < 4; i++) {
                if (td == 0) nacc[i] += wv[i];
#pragma unroll
                for (int j = 0; j < 4; j++) acc[i][j] = fmaf(wv[i], fv[j], acc[i][j]);
            }
        }
    }
    float* tok = g_tokens + (size_t)bh * NG * DH;
#pragma unroll
    for (int i = 0; i < 4; i++) {
#pragma unroll
        for (int j = 0; j < 4; j++) atomicAdd(&tok[(tg + i) * DH + td + j], acc[i][j]);
        if (td == 0) atomicAdd(&g_norms[bh * NG + tg + i], nacc[i]);
    }
}

// fused q/k/v projection + 64x64 self-attention per (b,h); W prefetched via cp.async
__global__ void k_qkvattn(const float* __restrict__ Wq, const float* __restrict__ bq,
                          const float* __restrict__ Wk, const float* __restrict__ bk,
                          const float* __restrict__ Wv, const float* __restrict__ bv) {
    int bh = blockIdx.x;
    extern __shared__ float fsm[];
    float* s_a = fsm;                 // [64][65]
    float* s_w = fsm + 64 * 65;       // 3 x [64][64]
    float* s_q = s_w + 3 * 4096;
    float* s_k = s_q + 4096;
    float* s_v = s_k + 4096;
    float* s_s = s_v + 4096;          // scores
    uint32_t sb = smem_to_u32(fsm);
    int t = threadIdx.x;
    const float* Ws[3] = {Wq, Wk, Wv};
    const float* bs[3] = {bq, bk, bv};
#pragma unroll
    for (int p = 0; p < 3; p++) {
        uint32_t dst = sb + (uint32_t)(64 * 65 + p * 4096) * 4;
        for (int i = t; i < 1024; i += 256)
            cp16(dst + i * 16, (const char*)Ws[p] + i * 16);
        CP_COMMIT();
    }
    for (int i = t; i < 4096; i += 256) {
        int g = i >> 6, d = i & 63;
        s_a[g * 65 + d] = g_tokens[(size_t)bh * 4096 + i] / (g_norms[bh * 64 + g] + 1e-5f);
    }
    int tx = t & 15, ty = t >> 4;
    float* outs[3] = {s_q, s_k, s_v};
#pragma unroll 1
    for (int p = 0; p < 3; p++) {
        if (p == 0) CP_WAIT2();
        else if (p == 1) CP_WAIT1();
        else CP_WAIT0();
        __syncthreads();
        const float* wp = s_w + p * 4096;
        float acc[4][4] = {};
        for (int k = 0; k < 64; k++) {
            float av[4], bv2[4];
#pragma unroll
            for (int i = 0; i < 4; i++) av[i] = s_a[(ty * 4 + i) * 65 + k];
#pragma unroll
            for (int j = 0; j < 4; j++) bv2[j] = wp[k * 64 + tx * 4 + j];
#pragma unroll
            for (int i = 0; i < 4; i++)
#pragma unroll
                for (int j = 0; j < 4; j++) acc[i][j] = fmaf(av[i], bv2[j], acc[i][j]);
        }
#pragma unroll
        for (int i = 0; i < 4; i++)
#pragma unroll
            for (int j = 0; j < 4; j++)
                outs[p][(ty * 4 + i) * 64 + tx * 4 + j] = acc[i][j] + bs[p][tx * 4 + j];
    }
    __syncthreads();
    {
        float acc[4][4] = {};
        for (int d = 0; d < 64; d++) {
            float av[4], bv2[4];
#pragma unroll
            for (int i = 0; i < 4; i++) av[i] = s_q[(ty * 4 + i) * 64 + d];
#pragma unroll
            for (int j = 0; j < 4; j++) bv2[j] = s_k[(tx * 4 + j) * 64 + d];
#pragma unroll
            for (int i = 0; i < 4; i++)
#pragma unroll
                for (int j = 0; j < 4; j++) acc[i][j] = fmaf(av[i], bv2[j], acc[i][j]);
        }
#pragma unroll
        for (int i = 0; i < 4; i++)
#pragma unroll
            for (int j = 0; j < 4; j++)
                s_s[(ty * 4 + i) * 64 + tx * 4 + j] = acc[i][j] * SCL;
    }
    __syncthreads();
    if (t < 64) {
        float m = -1e30f;
        for (int j = 0; j < 64; j++) m = fmaxf(m, s_s[t * 64 + j]);
        float s = 0.f;
        for (int j = 0; j < 64; j++) { float e = __expf(s_s[t * 64 + j] - m); s_s[t * 64 + j] = e; s += e; }
        float inv = 1.f / s;
        for (int j = 0; j < 64; j++) s_s[t * 64 + j] *= inv;
    }
    __syncthreads();
    float acc[4][4] = {};
    for (int k2 = 0; k2 < 64; k2++) {
        float av[4], bv2[4];
#pragma unroll
        for (int i = 0; i < 4; i++) av[i] = s_s[(ty * 4 + i) * 64 + k2];
#pragma unroll
        for (int j = 0; j < 4; j++) bv2[j] = s_v[k2 * 64 + tx * 4 + j];
#pragma unroll
        for (int i = 0; i < 4; i++)
#pragma unroll
            for (int j = 0; j < 4; j++) acc[i][j] = fmaf(av[i], bv2[j], acc[i][j]);
    }
#pragma unroll
    for (int i = 0; i < 4; i++)
#pragma unroll
        for (int j = 0; j < 4; j++)
            g_outtok[(size_t)bh * 4096 + (ty * 4 + i) * 64 + tx * 4 + j] = acc[i][j];
}

// sonata ks/vs projection: [32768x64] @ [64x64] + bias
__global__ void k_skv(const float* __restrict__ son,
                      const float* __restrict__ Wck, const float* __restrict__ bck,
                      const float* __restrict__ Wcv, const float* __restrict__ bcv) {
    int rt = blockIdx.x;
    int sel = blockIdx.y;
    const float* W = sel ? Wcv : Wck;
    const float* bias = sel ? bcv : bck;
    float* dst = sel ? g_vs : g_ks;
    __shared__ float s_at[64][65];
    __shared__ float s_b[64][64];
    int t = threadIdx.x;
    size_t base = (size_t)rt * 64 * 64;
    for (int i = t; i < 4096; i += 256) {
        s_at[i & 63][i >> 6] = son[base + i];
        s_b[i >> 6][i & 63] = W[i];
    }
    __syncthreads();
    int tx = t & 15, ty = t >> 4;
    float acc[4][4] = {};
    for (int k = 0; k < 64; k++) {
        float av[4], bv2[4];
#pragma unroll
        for (int i = 0; i < 4; i++) av[i] = s_at[k][ty * 4 + i];
#pragma unroll
        for (int j = 0; j < 4; j++) bv2[j] = s_b[k][tx * 4 + j];
#pragma unroll
        for (int i = 0; i < 4; i++)
#pragma unroll
            for (int j = 0; j < 4; j++) acc[i][j] = fmaf(av[i], bv2[j], acc[i][j]);
    }
#pragma unroll
    for (int i = 0; i < 4; i++)
#pragma unroll
        for (int j = 0; j < 4; j++)
            dst[base + (size_t)(ty * 4 + i) * 64 + tx * 4 + j] = acc[i][j] + bias[tx * 4 + j];
}

// cross-attention scores + per-slice online softmax partials: grid (64 bh, 8 slices)
__global__ void k_cross_score() {
    int bh = blockIdx.x, b = bh >> 3, h = bh & 7;
    int cnt = g_mcnt[b], start = g_mstart[b];
    if (cnt == 0) return;
    int sl = blockIdx.y;
    int lo = (int)(((long long)cnt * sl) >> 3);
    int hi = (int)(((long long)cnt * (sl + 1)) >> 3);
    int t = threadIdx.x;
    if (lo >= hi) {
        if (t < 64) g_pstat[((size_t)bh * 8 + sl) * 64 + t] = make_float2(-1e30f, 0.f);
        return;
    }
    __shared__ float s_q[64][65];
    __shared__ float s_kv[32][68];
    __shared__ float s_sc[64][33];
    __shared__ float row_m[64], row_s[64];
    __shared__ int mid[32];
    int tx = t & 15, ty = t >> 4;
    if (t < 64) { row_m[t] = -1e30f; row_s[t] = 0.f; }
    for (int i = t; i < 4096; i += 256) s_q[i >> 6][i & 63] = g_outtok[(size_t)bh * 4096 + i];
    __syncthreads();
    float* sc = g_scores + (size_t)bh * 64 * MS;
    for (int j0 = lo; j0 < hi; j0 += 32) {
        int nj = hi - j0; if (nj > 32) nj = 32;
        if (t < nj) mid[t] = g_mlist[start + j0 + t];
        __syncthreads();
        for (int i = t; i < nj * 64; i += 256) {
            int r = i >> 6, c = i & 63;
            s_kv[r][c] = g_ks[(size_t)mid[r] * DM + h * 64 + c];
        }
        __syncthreads();
        float acc[4][2] = {};
        int j1 = tx * 2;
        for (int d = 0; d < 64; d++) {
            float bv0 = s_kv[j1][d], bv1 = s_kv[j1 + 1][d];
#pragma unroll
            for (int i = 0; i < 4; i++) {
                float q = s_q[ty * 4 + i][d];
                acc[i][0] = fmaf(q, bv0, acc[i][0]);
                acc[i][1] = fmaf(q, bv1, acc[i][1]);
            }
        }
#pragma unroll
        for (int i = 0; i < 4; i++) {
            s_sc[ty * 4 + i][j1] = acc[i][0] * SCL;
            s_sc[ty * 4 + i][j1 + 1] = acc[i][1] * SCL;
        }
        __syncthreads();
        if (t < 64) {
            float cm = -1e30f;
            for (int j = 0; j < nj; j++) cm = fmaxf(cm, s_sc[t][j]);
            float cs = 0.f;
            for (int j = 0; j < nj; j++) cs += __expf(s_sc[t][j] - cm);
            float om = row_m[t], nm = fmaxf(om, cm);
            row_s[t] = row_s[t] * __expf(om - nm) + cs * __expf(cm - nm);
            row_m[t] = nm;
        }
        for (int i = t; i < 64 * 32; i += 256) {
            int g = i >> 5, j = i & 31;
            if (j < nj) sc[(size_t)g * MS + j0 + j] = s_sc[g][j];
        }
        __syncthreads();
    }
    if (t < 64) g_pstat[((size_t)bh * 8 + sl) * 64 + t] = make_float2(row_m[t], row_s[t]);
}

// cross-attention output: grid (64 bh, 8 j-slices); combines pstat inline, exp inline
__global__ void k_cross_out() {
    int bh = blockIdx.x, b = bh >> 3, h = bh & 7;
    int cnt = g_mcnt[b], start = g_mstart[b];
    if (cnt == 0) return;
    int sl = blockIdx.y;
    int lo = (int)(((long long)cnt * sl) >> 3);
    int hi = (int)(((long long)cnt * (sl + 1)) >> 3);
    if (lo >= hi) return;
    __shared__ float s_kv[32][64];
    __shared__ float s_cw[64][33];
    __shared__ float2 s_st[64];
    __shared__ int mid[32];
    int t = threadIdx.x;
    int tx = t & 15, ty = t >> 4;
    if (t < 64) {
        float m = -1e30f, s = 0.f;
#pragma unroll
        for (int p = 0; p < 8; p++) {
            float2 ps = g_pstat[((size_t)bh * 8 + p) * 64 + t];
            float nm = fmaxf(m, ps.x);
            s = s * __expf(m - nm) + ps.y * __expf(ps.x - nm);
            m = nm;
        }
        s_st[t] = make_float2(m, 1.f / s);
    }
    const float* sc = g_scores + (size_t)bh * 64 * MS;
    float acc[4][4] = {};
    for (int j0 = lo; j0 < hi; j0 += 32) {
        int nj = hi - j0; if (nj > 32) nj = 32;
        if (t < nj) mid[t] = g_mlist[start + j0 + t];
        __syncthreads();
        for (int i = t; i < nj * 64; i += 256) {
            int r = i >> 6, c = i & 63;
            s_kv[r][c] = g_vs[(size_t)mid[r] * DM + h * 64 + c];
        }
        for (int i = t; i < 64 * 32; i += 256) {
            int g = i >> 5, j = i & 31;
            float2 st = s_st[g];
            s_cw[g][j] = (j < nj) ? __expf(sc[(size_t)g * MS + j0 + j] - st.x) * st.y : 0.f;
        }
        __syncthreads();
        for (int j = 0; j < nj; j++) {
            float vvv[4];
#pragma unroll
            for (int jj = 0; jj < 4; jj++) vvv[jj] = s_kv[j][tx * 4 + jj];
#pragma unroll
            for (int i = 0; i < 4; i++) {
                float c = s_cw[ty * 4 + i][j];
#pragma unroll
                for (int jj = 0; jj < 4; jj++) acc[i][jj] = fmaf(c, vvv[jj], acc[i][jj]);
            }
        }
        __syncthreads();
    }
#pragma unroll
    for (int i = 0; i < 4; i++)
#pragma unroll
        for (int jj = 0; jj < 4; jj++)
            atomicAdd(&g_outtok[(size_t)bh * 4096 + (ty * 4 + i) * 64 + tx * 4 + jj], acc[i][jj]);
}

// P[b, h*64+g, c] = sum_d out_tok[b,h,g,d] * W_out[h*64+d, c], stored transposed bf16 hi/lo
__global__ void k_P(const float* __restrict__ Wout) {
    int bh = blockIdx.x, b = bh >> 3, h = bh & 7;
    int col0 = blockIdx.y * 64;
    __shared__ float s_a[64][65];
    __shared__ float s_b[64][64];
    int t = threadIdx.x;
    for (int i = t; i < 4096; i += 256) {
        int r = i >> 6, c = i & 63;
        s_a[r][c] = g_outtok[(size_t)bh * 4096 + i];
        s_b[r][c] = Wout[(size_t)(h * 64 + r) * DM + col0 + c];
    }
    __syncthreads();
    int tx = t & 15, ty = t >> 4;
    float acc[4][4] = {};
    for (int d = 0; d < 64; d++) {
        float av[4], bv[4];
#pragma unroll
        for (int i = 0; i < 4; i++) av[i] = s_a[ty * 4 + i][d];
#pragma unroll
        for (int j = 0; j < 4; j++) bv[j] = s_b[d][tx * 4 + j];
#pragma unroll
        for (int i = 0; i < 4; i++)
#pragma unroll
            for (int j = 0; j < 4; j++) acc[i][j] = fmaf(av[i], bv[j], acc[i][j]);
    }
#pragma unroll
    for (int i = 0; i < 4; i++)
#pragma unroll
        for (int j = 0; j < 4; j++) {
            int r = h * 64 + ty * 4 + i;       // k index of P
            int c = col0 + tx * 4 + j;         // output col
            __nv_bfloat16 hh, ll;
            bsplit(acc[i][j], hh, ll);
            g_Pthi[((size_t)b * DM + c) * DM + r] = hh;
            g_Ptlo[((size_t)b * DM + c) * DM + r] = ll;
        }
}

// out[n, :] = w[n, :] @ P[batch(n)] via mma.sync bf16x3, gathered rows, 3-stage pipeline
__global__ void __launch_bounds__(256, 2)
k_final_mma(float* __restrict__ out) {
    int b = blockIdx.z;
    int cnt = g_rowcnt[b];
    int r0 = blockIdx.y * 128;
    if (r0 >= cnt) return;
    int nr = cnt - r0; if (nr > 128) nr = 128;
    extern __shared__ char dynsmem[];
    uint32_t sb = smem_to_u32(dynsmem);
    __shared__ int rid[128];
    int t = threadIdx.x;
    int lane = t & 31, wid = t >> 5;
    int wm = (wid & 3) * 32, wn = (wid >> 2) * 64;
    int col0 = blockIdx.x * 128;
    int start = g_rowstart[b];
    if (t < 128) rid[t] = g_rowlist[start + r0 + (t < nr ? t : nr - 1)];
    __syncthreads();
    float acc[2][8][4] = {};
    int a_row = wm + (lane & 15);
    int a_u = lane >> 4;
    int b_row = wn + (lane & 7) + ((lane >> 4) << 3);
    int b_u = (lane >> 3) & 1;
    const __nv_bfloat16* Ph = g_Pthi + ((size_t)b * DM + col0) * DM;
    const __nv_bfloat16* Pl = g_Ptlo + ((size_t)b * DM + col0) * DM;

    auto load_slab = [&](int kc, int stg) {
        uint32_t sbase = sb + stg * STG_BYTES;
#pragma unroll
        for (int half = 0; half < 2; half++) {
            int idx = half * 256 + t;
            int r = idx >> 2, c = idx & 3;
            uint32_t o = SW64_((uint32_t)(r * 64 + c * 16));
            size_t offa = (size_t)rid[r] * DM + kc + c * 8;
            size_t offb = (size_t)r * DM + kc + c * 8;
            cp16(sbase + OFFS_AH + o, g_whi + offa);
            cp16(sbase + OFFS_AL + o, g_wlo + offa);
            cp16(sbase + OFFS_BH + o, Ph + offb);
            cp16(sbase + OFFS_BL + o, Pl + offb);
        }
        CP_COMMIT();
    };

    load_slab(0, 0);
    load_slab(KSLAB, 1);
#pragma unroll 1
    for (int ch = 0; ch < NSLAB; ch++) {
        if (ch + 2 < NSLAB) { load_slab((ch + 2) * KSLAB, (ch + 2) % 3); CP_WAIT2(); }
        else if (ch + 1 < NSLAB) { CP_WAIT1(); }
        else { CP_WAIT0(); }
        __syncthreads();
        uint32_t sbase = sb + (ch % 3) * STG_BYTES;
#pragma unroll
        for (int ks = 0; ks < 2; ks++) {
            uint32_t ah[2][4], al[2][4];
#pragma unroll
            for (int mt = 0; mt < 2; mt++) {
                uint32_t off = SW64_((uint32_t)((a_row + mt * 16) * 64 + ks * 32 + a_u * 16));
                ldsm4(ah[mt], sbase + OFFS_AH + off);
                ldsm4(al[mt], sbase + OFFS_AL + off);
            }
#pragma unroll
            for (int np = 0; np < 4; np++) {
                uint32_t bh[4], bl[4];
                uint32_t boff = SW64_((uint32_t)((b_row + np * 16) * 64 + ks * 32 + b_u * 16));
                ldsm4(bh, sbase + OFFS_BH + boff);
                ldsm4(bl, sbase + OFFS_BL + boff);
#pragma unroll
                for (int mt = 0; mt < 2; mt++) {
                    mma16816(acc[mt][np * 2 + 0], ah[mt], bh[0], bh[1]);
                    mma16816(acc[mt][np * 2 + 0], ah[mt], bl[0], bl[1]);
                    mma16816(acc[mt][np * 2 + 0], al[mt], bh[0], bh[1]);
                    mma16816(acc[mt][np * 2 + 1], ah[mt], bh[2], bh[3]);
                    mma16816(acc[mt][np * 2 + 1], ah[mt], bl[2], bl[3]);
                    mma16816(acc[mt][np * 2 + 1], al[mt], bh[2], bh[3]);
                }
            }
        }
        __syncthreads();
    }
    int g = lane >> 2, tig = lane & 3;
#pragma unroll
    for (int mt = 0; mt < 2; mt++)
#pragma unroll
        for (int nt = 0; nt < 8; nt++) {
            int ml = wm + mt * 16 + g;
            int c = col0 + wn + nt * 8 + tig * 2;
            if (ml < nr)
                *(float2*)(out + (size_t)rid[ml] * DM + c) =
                    make_float2(acc[mt][nt][0], acc[mt][nt][1]);
            if (ml + 8 < nr)
                *(float2*)(out + (size_t)rid[ml + 8] * DM + c) =
                    make_float2(acc[mt][nt][2], acc[mt][nt][3]);
        }
}

extern "C" void kernel_launch(void* const* d_in, const int* in_sizes, int n_in,
                              void* d_out, int out_size) {
    const float* x    = (const float*)d_in[0];
    const int*   bi   = (const int*)d_in[1];
    const float* son  = (const float*)d_in[2];
    const int*   sbi  = (const int*)d_in[3];
    const float* temp = (const float*)d_in[4];
    const float* Wfx  = (const float*)d_in[5];
    const float* bfx  = (const float*)d_in[6];
    const float* Wx   = (const float*)d_in[7];
    const float* bx   = (const float*)d_in[8];
    const float* Wsl  = (const float*)d_in[9];
    const float* bsl  = (const float*)d_in[10];
    const float* Wq   = (const float*)d_in[11];
    const float* bq   = (const float*)d_in[12];
    const float* Wk   = (const float*)d_in[13];
    const float* bk   = (const float*)d_in[14];
    const float* Wv   = (const float*)d_in[15];
    const float* bv   = (const float*)d_in[16];
    const float* Wck  = (const float*)d_in[17];
    const float* bck  = (const float*)d_in[18];
    const float* Wcv  = (const float*)d_in[19];
    const float* bcv  = (const float*)d_in[20];
    const float* Wout = (const float*)d_in[21];
    float* out = (float*)d_out;

    static cudaStream_t s1 = nullptr, s2 = nullptr;
    static cudaEvent_t eF = nullptr, e1 = nullptr, e2a = nullptr, e2b = nullptr;
    if (s1 == nullptr) {
        cudaStreamCreateWithFlags(&s1, cudaStreamNonBlocking);
        cudaStreamCreateWithFlags(&s2, cudaStreamNonBlocking);
        cudaEventCreateWithFlags(&eF, cudaEventDisableTiming);
        cudaEventCreateWithFlags(&e1, cudaEventDisableTiming);
        cudaEventCreateWithFlags(&e2a, cudaEventDisableTiming);
        cudaEventCreateWithFlags(&e2b, cudaEventDisableTiming);
        cudaFuncSetAttribute(k_gemm_mma, cudaFuncAttributeMaxDynamicSharedMemorySize, SMEM_MMA);
        cudaFuncSetAttribute(k_final_mma, cudaFuncAttributeMaxDynamicSharedMemorySize, SMEM_MMA);
        cudaFuncSetAttribute(k_qkvattn, cudaFuncAttributeMaxDynamicSharedMemorySize, QKV_SMEM);
    }

    // fork
    cudaEventRecord(eF, 0);
    cudaStreamWaitEvent(s1, eF, 0);
    cudaStreamWaitEvent(s2, eF, 0);

    // stream s1: batch bucketing chain (independent of x path)
    k_zero<<<1024, 256, 0, s1>>>();
    k_count<<<80, 256, 0, s1>>>(bi, sbi);
    k_prefix<<<1, 1, 0, s1>>>();
    k_scatter<<<80, 256, 0, s1>>>(bi, sbi);
    cudaEventRecord(e1, s1);

    // stream s2: bias fold + weight transpose (feed gemm), then sonata K/V projection
    k_bcomb<<<1, 512, 0, s2>>>(bx, Wsl, bsl);
    k_wcomb<<<dim3(512, 2), 256, 0, s2>>>(Wx, Wsl, Wfx);
    cudaEventRecord(e2a, s2);
    k_skv<<<dim3(512, 2), 256, 0, s2>>>(son, Wck, bck, Wcv, bcv);
    cudaEventRecord(e2b, s2);

    // main stream
    k_cvt_x<<<8192, 256>>>(x);
    cudaStreamWaitEvent(0, e2a, 0);
    k_gemm_mma<<<dim3(8, 128), 256, SMEM_MMA>>>(bfx, temp);
    cudaStreamWaitEvent(0, e1, 0);
    k_tokens<<<dim3(64, 32), 256>>>();
    k_qkvattn<<<64, 256, QKV_SMEM>>>(Wq, bq, Wk, bk, Wv, bv);
    cudaStreamWaitEvent(0, e2b, 0);
    k_cross_score<<<dim3(64, 8), 256>>>();
    k_cross_out<<<dim3(64, 8), 256>>>();
    k_P<<<dim3(64, 8), 256>>>(Wout);
    k_final_mma<<<dim3(4, 128, 8), 256, SMEM_MMA>>>(out);
}

// round 17
// speedup vs baseline: 1.0119x; 1.0119x over previous
#include <cuda_runtime.h>
#include <cuda_bf16.h>
#include <cstdint>

#define NT 16384   // x rows
#define MS 4096    // sonata rows
#define NB 8       // batches
#define NH 8       // heads
#define DH 64      // head dim
#define NG 64      // slice groups
#define DM 512     // model dim
#define SCL 0.125f // D^-0.5

#define SW64_(o) ((o) ^ (((o) >> 3) & 0x30))

__device__ __forceinline__ uint32_t smem_to_u32(const void* p) {
    uint32_t a;
    asm("{ .reg .u64 tmp; cvta.to.shared.u64 tmp, %1; cvt.u32.u64 %0, tmp; }"
        : "=r"(a) : "l"(p));
    return a;
}
__device__ __forceinline__ void ldsm4(uint32_t a[4], uint32_t addr) {
    asm volatile("ldmatrix.sync.aligned.m8n8.x4.shared.b16 {%0,%1,%2,%3}, [%4];"
                 : "=r"(a[0]), "=r"(a[1]), "=r"(a[2]), "=r"(a[3]) : "r"(addr));
}
__device__ __forceinline__ void mma16816(float c[4], const uint32_t a[4],
                                         uint32_t b0, uint32_t b1) {
    asm volatile(
        "mma.sync.aligned.m16n8k16.row.col.f32.bf16.bf16.f32 "
        "{%0,%1,%2,%3}, {%4,%5,%6,%7}, {%8,%9}, {%0,%1,%2,%3};"
        : "+f"(c[0]), "+f"(c[1]), "+f"(c[2]), "+f"(c[3])
        : "r"(a[0]), "r"(a[1]), "r"(a[2]), "r"(a[3]), "r"(b0), "r"(b1));
}
__device__ __forceinline__ void cp16(uint32_t dst, const void* src) {
    asm volatile("cp.async.cg.shared.global [%0], [%1], 16;" :: "r"(dst), "l"(src));
}
#define CP_COMMIT() asm volatile("cp.async.commit_group;" ::: "memory")
#define CP_WAIT2() asm volatile("cp.async.wait_group 2;" ::: "memory")
#define CP_WAIT1() asm volatile("cp.async.wait_group 1;" ::: "memory")
#define CP_WAIT0() asm volatile("cp.async.wait_group 0;" ::: "memory")

__device__ __forceinline__ void bsplit(float v, __nv_bfloat16& h, __nv_bfloat16& l) {
    h = __float2bfloat16(v);
    l = __float2bfloat16(v - __bfloat162float(h));
}

// pipelined MMA smem: 3 stages x (AH 8K | AL 8K | BH 8K | BL 8K) = 96KB
#define STG_BYTES 32768
#define OFFS_AH 0
#define OFFS_AL 8192
#define OFFS_BH 16384
#define OFFS_BL 24576
#define SMEM_MMA (3 * STG_BYTES)
#define KSLAB 32
#define NSLAB (DM / KSLAB)

// fused qkv+attn smem: a[64][65] + 3x W[64][64] + q,k,v[64][64] + s[64][64]
#define QKV_SMEM ((64 * 65 + 3 * 4096 + 3 * 4096 + 4096) * 4)

// ---------------- device scratch ----------------
__device__ float g_bcomb[DM];
__device__ float g_fx[(size_t)NT * DM];
__device__ __nv_bfloat16 g_xhi[(size_t)NT * DM], g_xlo[(size_t)NT * DM];
__device__ __nv_bfloat16 g_Bthi[(size_t)2 * DM * DM], g_Btlo[(size_t)2 * DM * DM]; // [1024][512]
__device__ __nv_bfloat16 g_whi[(size_t)NT * DM], g_wlo[(size_t)NT * DM];
__device__ __nv_bfloat16 g_Pthi[(size_t)NB * DM * DM], g_Ptlo[(size_t)NB * DM * DM]; // [b][c][k]
__device__ float g_tokens[NB * NH * NG * DH];
__device__ float g_norms[NB * NH * NG];
__device__ float g_outtok[NB * NH * NG * DH];
__device__ float g_ks[(size_t)MS * DM];
__device__ float g_vs[(size_t)MS * DM];
__device__ float g_scores[(size_t)NB * NH * NG * MS];
__device__ float2 g_pstat[NB * NH * 8 * NG];    // per-(bh,slice,g) partial (m, s)
__device__ int g_rowlist[NT], g_rowcnt[NB], g_rowstart[NB + 1], g_rowcur[NB];
__device__ int g_mlist[MS], g_mcnt[NB], g_mstart[NB + 1], g_mcur[NB];

// ---------------- setup kernels ----------------
__global__ void k_zero() {
    int i = blockIdx.x * 256 + threadIdx.x;
    if (i < NB * NH * NG * DH) g_tokens[i] = 0.f;
    if (i < NB * NH * NG) g_norms[i] = 0.f;
    if (i < NB) {
        g_rowcnt[i] = 0; g_mcnt[i] = 0;
        g_rowcur[i] = 0; g_mcur[i] = 0;
    }
}

__global__ void k_bcomb(const float* __restrict__ bx, const float* __restrict__ Wsl,
                        const float* __restrict__ bsl) {
    int o = threadIdx.x;  // 512
    int h = o >> 6, g = o & 63;
    float acc = bsl[g];
    for (int d = 0; d < 64; d++) acc = fmaf(bx[h * 64 + d], Wsl[d * 64 + g], acc);
    g_bcomb[o] = acc;
}

// x fp32 -> bf16 hi/lo split
__global__ void k_cvt_x(const float* __restrict__ x) {
    size_t i = (size_t)blockIdx.x * 256 + threadIdx.x;  // one float4 each
    float4 v = ((const float4*)x)[i];
    __nv_bfloat16 h0, h1, h2, h3, l0, l1, l2, l3;
    bsplit(v.x, h0, l0); bsplit(v.y, h1, l1);
    bsplit(v.z, h2, l2); bsplit(v.w, h3, l3);
    ((__nv_bfloat162*)g_xhi)[i * 2 + 0] = __halves2bfloat162(h0, h1);
    ((__nv_bfloat162*)g_xhi)[i * 2 + 1] = __halves2bfloat162(h2, h3);
    ((__nv_bfloat162*)g_xlo)[i * 2 + 0] = __halves2bfloat162(l0, l1);
    ((__nv_bfloat162*)g_xlo)[i * 2 + 1] = __halves2bfloat162(l2, l3);
}

// y==1: Bt rows 0..511 (transposed Wfx); y==0: Bt rows 512..1023 from Wcomb = Wx·Wsl
__global__ void k_wcomb(const float* __restrict__ Wx, const float* __restrict__ Wsl,
                        const float* __restrict__ Wfx) {
    int c = blockIdx.x;  // 0..511
    int t = threadIdx.x;
    if (blockIdx.y == 1) {
        for (int k = t; k < DM; k += 256) {
            __nv_bfloat16 h, l;
            bsplit(Wfx[(size_t)k * DM + c], h, l);
            g_Bthi[(size_t)c * DM + k] = h;
            g_Btlo[(size_t)c * DM + k] = l;
        }
        return;
    }
    __shared__ float s_sl[4096];
    for (int i = t; i < 4096; i += 256) s_sl[i] = Wsl[i];
    __syncthreads();
    for (int o = t; o < 512; o += 256) {
        int h = o >> 6, g = o & 63;
        const float* wxr = Wx + (size_t)c * DM + h * 64;
        float acc = 0.f;
        for (int d = 0; d < 64; d++) acc = fmaf(wxr[d], s_sl[d * 64 + g], acc);
        __nv_bfloat16 hh, ll;
        bsplit(acc, hh, ll);
        g_Bthi[(size_t)(DM + o) * DM + c] = hh;
        g_Btlo[(size_t)(DM + o) * DM + c] = ll;
    }
}

__global__ void k_count(const int* __restrict__ bi, const int* __restrict__ sbi) {
    int i = blockIdx.x * 256 + threadIdx.x;
    if (i < NT) atomicAdd(&g_rowcnt[bi[i]], 1);
    else if (i < NT + MS) atomicAdd(&g_mcnt[sbi[i - NT]], 1);
}

__global__ void k_prefix() {
    if (threadIdx.x == 0) {
        int s = 0;
        for (int b = 0; b < NB; b++) { g_rowstart[b] = s; s += g_rowcnt[b]; }
        g_rowstart[NB] = s;
        s = 0;
        for (int b = 0; b < NB; b++) { g_mstart[b] = s; s += g_mcnt[b]; }
        g_mstart[NB] = s;
    }
}

__global__ void k_scatter(const int* __restrict__ bi, const int* __restrict__ sbi) {
    int i = blockIdx.x * 256 + threadIdx.x;
    if (i < NT) {
        int b = bi[i];
        int p = atomicAdd(&g_rowcur[b], 1);
        g_rowlist[g_rowstart[b] + p] = i;
    } else if (i < NT + MS) {
        int j = i - NT;
        int b = sbi[j];
        int p = atomicAdd(&g_mcur[b], 1);
        g_mlist[g_mstart[b] + p] = j;
    }
}

// ---------------- front GEMM via mma.sync bf16x3, 3-stage pipeline, fused slice-softmax ----------------
__global__ void __launch_bounds__(256, 2)
k_gemm_mma(const float* __restrict__ bfx, const float* __restrict__ temp) {
    extern __shared__ char dynsmem[];
    uint32_t sb = smem_to_u32(dynsmem);
    int t = threadIdx.x;
    int lane = t & 31, wid = t >> 5;
    int wm = (wid & 3) * 32, wn = (wid >> 2) * 64;
    int row0 = blockIdx.y * 128, col0 = blockIdx.x * 128;
    float acc[2][8][4] = {};
    int a_row = wm + (lane & 15);
    int a_u = lane >> 4;
    int b_row = wn + (lane & 7) + ((lane >> 4) << 3);
    int b_u = (lane >> 3) & 1;

    auto load_slab = [&](int kc, int stg) {
        uint32_t sbase = sb + stg * STG_BYTES;
#pragma unroll
        for (int half = 0; half < 2; half++) {
            int idx = half * 256 + t;
            int r = idx >> 2, c = idx & 3;
            uint32_t o = SW64_((uint32_t)(r * 64 + c * 16));
            size_t offa = (size_t)(row0 + r) * DM + kc + c * 8;
            size_t offb = (size_t)(col0 + r) * DM + kc + c * 8;
            cp16(sbase + OFFS_AH + o, g_xhi + offa);
            cp16(sbase + OFFS_AL + o, g_xlo + offa);
            cp16(sbase + OFFS_BH + o, g_Bthi + offb);
            cp16(sbase + OFFS_BL + o, g_Btlo + offb);
        }
        CP_COMMIT();
    };

    load_slab(0, 0);
    load_slab(KSLAB, 1);
#pragma unroll 1
    for (int ch = 0; ch < NSLAB; ch++) {
        if (ch + 2 < NSLAB) { load_slab((ch + 2) * KSLAB, (ch + 2) % 3); CP_WAIT2(); }
        else if (ch + 1 < NSLAB) { CP_WAIT1(); }
        else { CP_WAIT0(); }
        __syncthreads();
        uint32_t sbase = sb + (ch % 3) * STG_BYTES;
#pragma unroll
        for (int ks = 0; ks < 2; ks++) {
            uint32_t ah[2][4], al[2][4];
#pragma unroll
            for (int mt = 0; mt < 2; mt++) {
                uint32_t off = SW64_((uint32_t)((a_row + mt * 16) * 64 + ks * 32 + a_u * 16));
                ldsm4(ah[mt], sbase + OFFS_AH + off);
                ldsm4(al[mt], sbase + OFFS_AL + off);
            }
#pragma unroll
            for (int np = 0; np < 4; np++) {
                uint32_t bh[4], bl[4];
                uint32_t boff = SW64_((uint32_t)((b_row + np * 16) * 64 + ks * 32 + b_u * 16));
                ldsm4(bh, sbase + OFFS_BH + boff);
                ldsm4(bl, sbase + OFFS_BL + boff);
#pragma unroll
                for (int mt = 0; mt < 2; mt++) {
                    mma16816(acc[mt][np * 2 + 0], ah[mt], bh[0], bh[1]);
                    mma16816(acc[mt][np * 2 + 0], ah[mt], bl[0], bl[1]);
                    mma16816(acc[mt][np * 2 + 0], al[mt], bh[0], bh[1]);
                    mma16816(acc[mt][np * 2 + 1], ah[mt], bh[2], bh[3]);
                    mma16816(acc[mt][np * 2 + 1], ah[mt], bl[2], bl[3]);
                    mma16816(acc[mt][np * 2 + 1], al[mt], bh[2], bh[3]);
                }
            }
        }
        __syncthreads();
    }
    int g = lane >> 2, tig = lane & 3;
    bool isfx = (col0 < DM);
    if (isfx) {
#pragma unroll
        for (int mt = 0; mt < 2; mt++)
#pragma unroll
            for (int nt = 0; nt < 8; nt++) {
                int r1 = row0 + wm + mt * 16 + g;
                int c = col0 + wn + nt * 8 + tig * 2;
                float b0v = bfx[c], b1v = bfx[c + 1];
                *(float2*)(g_fx + (size_t)r1 * DM + c) =
                    make_float2(acc[mt][nt][0] + b0v, acc[mt][nt][1] + b1v);
                *(float2*)(g_fx + (size_t)(r1 + 8) * DM + c) =
                    make_float2(acc[mt][nt][2] + b0v, acc[mt][nt][3] + b1v);
            }
    } else {
        // fused slice softmax; w stored only as bf16 hi/lo split
        int cbase = col0 - DM;
        int h = (cbase + wn) >> 6;
        float it = 1.f / temp[h];
#pragma unroll
        for (int mt = 0; mt < 2; mt++)
#pragma unroll
            for (int half = 0; half < 2; half++) {
                int r1 = row0 + wm + mt * 16 + g + half * 8;
                float v[16];
#pragma unroll
                for (int nt = 0; nt < 8; nt++) {
                    int c = cbase + wn + nt * 8 + tig * 2;
                    v[nt * 2 + 0] = (acc[mt][nt][half * 2 + 0] + g_bcomb[c]) * it;
                    v[nt * 2 + 1] = (acc[mt][nt][half * 2 + 1] + g_bcomb[c + 1]) * it;
                }
                float m = v[0];
#pragma unroll
                for (int i = 1; i < 16; i++) m = fmaxf(m, v[i]);
                m = fmaxf(m, __shfl_xor_sync(0xFFFFFFFFu, m, 1));
                m = fmaxf(m, __shfl_xor_sync(0xFFFFFFFFu, m, 2));
                float s = 0.f;
#pragma unroll
                for (int i = 0; i < 16; i++) { v[i] = __expf(v[i] - m); s += v[i]; }
                s += __shfl_xor_sync(0xFFFFFFFFu, s, 1);
                s += __shfl_xor_sync(0xFFFFFFFFu, s, 2);
                float inv = 1.f / s;
#pragma unroll
                for (int nt = 0; nt < 8; nt++) {
                    int cw = cbase + wn + nt * 8 + tig * 2;
                    float w0 = v[nt * 2 + 0] * inv, w1 = v[nt * 2 + 1] * inv;
                    __nv_bfloat16 h0, l0, h1, l1;
                    bsplit(w0, h0, l0); bsplit(w1, h1, l1);
                    *(__nv_bfloat162*)(g_whi + (size_t)r1 * DM + cw) = __halves2bfloat162(h0, h1);
                    *(__nv_bfloat162*)(g_wlo + (size_t)r1 * DM + cw) = __halves2bfloat162(l0, l1);
                }
            }
    }
}

// tokens[b,h,g,d] = sum_{n in b} w[n,h,g] * fx[n,h,d]; norms[b,h,g] = sum w
// grid (64 bh, 32 row-slices); w reconstructed from bf16 hi+lo
__global__ void k_tokens() {
    int bh = blockIdx.x;
    int b = bh >> 3, h = bh & 7;
    int cnt = g_rowcnt[b], start = g_rowstart[b];
    int c0 = (int)(((long long)cnt * blockIdx.y) >> 5);
    int c1 = (int)(((long long)cnt * (blockIdx.y + 1)) >> 5);
    int t = threadIdx.x;
    int tg = (t >> 4) * 4, td = (t & 15) * 4;
    float acc[4][4] = {};
    float nacc[4] = {};
    __shared__ float ws[16][64], fs[16][64];
    __shared__ int rid[16];
    for (int i0 = c0; i0 < c1; i0 += 16) {
        int nr = c1 - i0; if (nr > 16) nr = 16;
        if (t < nr) rid[t] = g_rowlist[start + i0 + t];
        __syncthreads();
        for (int idx = t; idx < nr * 64; idx += 256) {
            int r = idx >> 6, c = idx & 63;
            size_t off = (size_t)rid[r] * DM + h * 64 + c;
            ws[r][c] = __bfloat162float(g_whi[off]) + __bfloat162float(g_wlo[off]);
            fs[r][c] = g_fx[off];
        }
        __syncthreads();
        for (int r = 0; r < nr; r++) {
            float wv[4], fv[4];
#pragma unroll
            for (int i = 0; i < 4; i++) { wv[i] = ws[r][tg + i]; fv[i] = fs[r][td + i]; }
#pragma unroll
            for (int i = 0; i < 4; i++) {
                if (td == 0) nacc[i] += wv[i];
#pragma unroll
                for (int j = 0; j < 4; j++) acc[i][j] = fmaf(wv[i], fv[j], acc[i][j]);
            }
        }
        __syncthreads();
    }
    float* tok = g_tokens + (size_t)bh * NG * DH;
#pragma unroll
    for (int i = 0; i < 4; i++) {
#pragma unroll
        for (int j = 0; j < 4; j++) atomicAdd(&tok[(tg + i) * DH + td + j], acc[i][j]);
        if (td == 0) atomicAdd(&g_norms[bh * NG + tg + i], nacc[i]);
    }
}

// fused q/k/v projection + 64x64 self-attention per (b,h); W prefetched via cp.async
__global__ void k_qkvattn(const float* __restrict__ Wq, const float* __restrict__ bq,
                          const float* __restrict__ Wk, const float* __restrict__ bk,
                          const float* __restrict__ Wv, const float* __restrict__ bv) {
    int bh = blockIdx.x;
    extern __shared__ float fsm[];
    float* s_a = fsm;                 // [64][65]
    float* s_w = fsm + 64 * 65;       // 3 x [64][64]
    float* s_q = s_w + 3 * 4096;
    float* s_k = s_q + 4096;
    float* s_v = s_k + 4096;
    float* s_s = s_v + 4096;          // scores
    uint32_t sb = smem_to_u32(fsm);
    int t = threadIdx.x;
    const float* Ws[3] = {Wq, Wk, Wv};
    const float* bs[3] = {bq, bk, bv};
#pragma unroll
    for (int p = 0; p < 3; p++) {
        uint32_t dst = sb + (uint32_t)(64 * 65 + p * 4096) * 4;
        for (int i = t; i < 1024; i += 256)
            cp16(dst + i * 16, (const char*)Ws[p] + i * 16);
        CP_COMMIT();
    }
    for (int i = t; i < 4096; i += 256) {
        int g = i >> 6, d = i & 63;
        s_a[g * 65 + d] = g_tokens[(size_t)bh * 4096 + i] / (g_norms[bh * 64 + g] + 1e-5f);
    }
    int tx = t & 15, ty = t >> 4;
    float* outs[3] = {s_q, s_k, s_v};
#pragma unroll 1
    for (int p = 0; p < 3; p++) {
        if (p == 0) CP_WAIT2();
        else if (p == 1) CP_WAIT1();
        else CP_WAIT0();
        __syncthreads();
        const float* wp = s_w + p * 4096;
        float acc[4][4] = {};
        for (int k = 0; k < 64; k++) {
            float av[4], bv2[4];
#pragma unroll
            for (int i = 0; i < 4; i++) av[i] = s_a[(ty * 4 + i) * 65 + k];
#pragma unroll
            for (int j = 0; j < 4; j++) bv2[j] = wp[k * 64 + tx * 4 + j];
#pragma unroll
            for (int i = 0; i < 4; i++)
#pragma unroll
                for (int j = 0; j < 4; j++) acc[i][j] = fmaf(av[i], bv2[j], acc[i][j]);
        }
#pragma unroll
        for (int i = 0; i < 4; i++)
#pragma unroll
            for (int j = 0; j < 4; j++)
                outs[p][(ty * 4 + i) * 64 + tx * 4 + j] = acc[i][j] + bs[p][tx * 4 + j];
    }
    __syncthreads();
    {
        float acc[4][4] = {};
        for (int d = 0; d < 64; d++) {
            float av[4], bv2[4];
#pragma unroll
            for (int i = 0; i < 4; i++) av[i] = s_q[(ty * 4 + i) * 64 + d];
#pragma unroll
            for (int j = 0; j < 4; j++) bv2[j] = s_k[(tx * 4 + j) * 64 + d];
#pragma unroll
            for (int i = 0; i < 4; i++)
#pragma unroll
                for (int j = 0; j < 4; j++) acc[i][j] = fmaf(av[i], bv2[j], acc[i][j]);
        }
#pragma unroll
        for (int i = 0; i < 4; i++)
#pragma unroll
            for (int j = 0; j < 4; j++)
                s_s[(ty * 4 + i) * 64 + tx * 4 + j] = acc[i][j] * SCL;
    }
    __syncthreads();
    if (t < 64) {
        float m = -1e30f;
        for (int j = 0; j < 64; j++) m = fmaxf(m, s_s[t * 64 + j]);
        float s = 0.f;
        for (int j = 0; j < 64; j++) { float e = __expf(s_s[t * 64 + j] - m); s_s[t * 64 + j] = e; s += e; }
        float inv = 1.f / s;
        for (int j = 0; j < 64; j++) s_s[t * 64 + j] *= inv;
    }
    __syncthreads();
    float acc[4][4] = {};
    for (int k2 = 0; k2 < 64; k2++) {
        float av[4], bv2[4];
#pragma unroll
        for (int i = 0; i < 4; i++) av[i] = s_s[(ty * 4 + i) * 64 + k2];
#pragma unroll
        for (int j = 0; j < 4; j++) bv2[j] = s_v[k2 * 64 + tx * 4 + j];
#pragma unroll
        for (int i = 0; i < 4; i++)
#pragma unroll
            for (int j = 0; j < 4; j++) acc[i][j] = fmaf(av[i], bv2[j], acc[i][j]);
    }
#pragma unroll
    for (int i = 0; i < 4; i++)
#pragma unroll
        for (int j = 0; j < 4; j++)
            g_outtok[(size_t)bh * 4096 + (ty * 4 + i) * 64 + tx * 4 + j] = acc[i][j];
}

// sonata ks/vs projection: [32768x64] @ [64x64] + bias
__global__ void k_skv(const float* __restrict__ son,
                      const float* __restrict__ Wck, const float* __restrict__ bck,
                      const float* __restrict__ Wcv, const float* __restrict__ bcv) {
    int rt = blockIdx.x;
    int sel = blockIdx.y;
    const float* W = sel ? Wcv : Wck;
    const float* bias = sel ? bcv : bck;
    float* dst = sel ? g_vs : g_ks;
    __shared__ float s_at[64][65];
    __shared__ float s_b[64][64];
    int t = threadIdx.x;
    size_t base = (size_t)rt * 64 * 64;
    for (int i = t; i < 4096; i += 256) {
        s_at[i & 63][i >> 6] = son[base + i];
        s_b[i >> 6][i & 63] = W[i];
    }
    __syncthreads();
    int tx = t & 15, ty = t >> 4;
    float acc[4][4] = {};
    for (int k = 0; k < 64; k++) {
        float av[4], bv2[4];
#pragma unroll
        for (int i = 0; i < 4; i++) av[i] = s_at[k][ty * 4 + i];
#pragma unroll
        for (int j = 0; j < 4; j++) bv2[j] = s_b[k][tx * 4 + j];
#pragma unroll
        for (int i = 0; i < 4; i++)
#pragma unroll
            for (int j = 0; j < 4; j++) acc[i][j] = fmaf(av[i], bv2[j], acc[i][j]);
    }
#pragma unroll
    for (int i = 0; i < 4; i++)
#pragma unroll
        for (int j = 0; j < 4; j++)
            dst[base + (size_t)(ty * 4 + i) * 64 + tx * 4 + j] = acc[i][j] + bias[tx * 4 + j];
}

// cross-attention scores + per-slice online softmax partials: grid (64 bh, 8 slices)
__global__ void k_cross_score() {
    int bh = blockIdx.x, b = bh >> 3, h = bh & 7;
    int cnt = g_mcnt[b], start = g_mstart[b];
    if (cnt == 0) return;
    int sl = blockIdx.y;
    int lo = (int)(((long long)cnt * sl) >> 3);
    int hi = (int)(((long long)cnt * (sl + 1)) >> 3);
    int t = threadIdx.x;
    if (lo >= hi) {
        if (t < 64) g_pstat[((size_t)bh * 8 + sl) * 64 + t] = make_float2(-1e30f, 0.f);
        return;
    }
    __shared__ float s_q[64][65];
    __shared__ float s_kv[32][68];
    __shared__ float s_sc[64][33];
    __shared__ float row_m[64], row_s[64];
    __shared__ int mid[32];
    int tx = t & 15, ty = t >> 4;
    if (t < 64) { row_m[t] = -1e30f; row_s[t] = 0.f; }
    for (int i = t; i < 4096; i += 256) s_q[i >> 6][i & 63] = g_outtok[(size_t)bh * 4096 + i];
    __syncthreads();
    float* sc = g_scores + (size_t)bh * 64 * MS;
    for (int j0 = lo; j0 < hi; j0 += 32) {
        int nj = hi - j0; if (nj > 32) nj = 32;
        if (t < nj) mid[t] = g_mlist[start + j0 + t];
        __syncthreads();
        for (int i = t; i < nj * 64; i += 256) {
            int r = i >> 6, c = i & 63;
            s_kv[r][c] = g_ks[(size_t)mid[r] * DM + h * 64 + c];
        }
        __syncthreads();
        float acc[4][2] = {};
        int j1 = tx * 2;
        for (int d = 0; d < 64; d++) {
            float bv0 = s_kv[j1][d], bv1 = s_kv[j1 + 1][d];
#pragma unroll
            for (int i = 0; i < 4; i++) {
                float q = s_q[ty * 4 + i][d];
                acc[i][0] = fmaf(q, bv0, acc[i][0]);
                acc[i][1] = fmaf(q, bv1, acc[i][1]);
            }
        }
#pragma unroll
        for (int i = 0; i < 4; i++) {
            s_sc[ty * 4 + i][j1] = acc[i][0] * SCL;
            s_sc[ty * 4 + i][j1 + 1] = acc[i][1] * SCL;
        }
        __syncthreads();
        if (t < 64) {
            float cm = -1e30f;
            for (int j = 0; j < nj; j++) cm = fmaxf(cm, s_sc[t][j]);
            float cs = 0.f;
            for (int j = 0; j < nj; j++) cs += __expf(s_sc[t][j] - cm);
            float om = row_m[t], nm = fmaxf(om, cm);
            row_s[t] = row_s[t] * __expf(om - nm) + cs * __expf(cm - nm);
            row_m[t] = nm;
        }
        for (int i = t; i < 64 * 32; i += 256) {
            int g = i >> 5, j = i & 31;
            if (j < nj) sc[(size_t)g * MS + j0 + j] = s_sc[g][j];
        }
        __syncthreads();
    }
    if (t < 64) g_pstat[((size_t)bh * 8 + sl) * 64 + t] = make_float2(row_m[t], row_s[t]);
}

// cross-attention output: grid (64 bh, 8 j-slices); combines pstat inline, exp inline
__global__ void k_cross_out() {
    int bh = blockIdx.x, b = bh >> 3, h = bh & 7;
    int cnt = g_mcnt[b], start = g_mstart[b];
    if (cnt == 0) return;
    int sl = blockIdx.y;
    int lo = (int)(((long long)cnt * sl) >> 3);
    int hi = (int)(((long long)cnt * (sl + 1)) >> 3);
    if (lo >= hi) return;
    __shared__ float s_kv[32][64];
    __shared__ float s_cw[64][33];
    __shared__ float2 s_st[64];
    __shared__ int mid[32];
    int t = threadIdx.x;
    int tx = t & 15, ty = t >> 4;
    if (t < 64) {
        float m = -1e30f, s = 0.f;
#pragma unroll
        for (int p = 0; p < 8; p++) {
            float2 ps = g_pstat[((size_t)bh * 8 + p) * 64 + t];
            float nm = fmaxf(m, ps.x);
            s = s * __expf(m - nm) + ps.y * __expf(ps.x - nm);
            m = nm;
        }
        s_st[t] = make_float2(m, 1.f / s);
    }
    const float* sc = g_scores + (size_t)bh * 64 * MS;
    float acc[4][4] = {};
    for (int j0 = lo; j0 < hi; j0 += 32) {
        int nj = hi - j0; if (nj > 32) nj = 32;
        if (t < nj) mid[t] = g_mlist[start + j0 + t];
        __syncthreads();
        for (int i = t; i < nj * 64; i += 256) {
            int r = i >> 6, c = i & 63;
            s_kv[r][c] = g_vs[(size_t)mid[r] * DM + h * 64 + c];
        }
        for (int i = t; i < 64 * 32; i += 256) {
            int g = i >> 5, j = i & 31;
            float2 st = s_st[g];
            s_cw[g][j] = (j < nj) ? __expf(sc[(size_t)g * MS + j0 + j] - st.x) * st.y : 0.f;
        }
        __syncthreads();
        for (int j = 0; j < nj; j++) {
            float vvv[4];
#pragma unroll
            for (int jj = 0; jj < 4; jj++) vvv[jj] = s_kv[j][tx * 4 + jj];
#pragma unroll
            for (int i = 0; i < 4; i++) {
                float c = s_cw[ty * 4 + i][j];
#pragma unroll
                for (int jj = 0; jj < 4; jj++) acc[i][jj] = fmaf(c, vvv[jj], acc[i][jj]);
            }
        }
        __syncthreads();
    }
#pragma unroll
    for (int i = 0; i < 4; i++)
#pragma unroll
        for (int jj = 0; jj < 4; jj++)
            atomicAdd(&g_outtok[(size_t)bh * 4096 + (ty * 4 + i) * 64 + tx * 4 + jj], acc[i][jj]);
}

// P[b, h*64+g, c] = sum_d out_tok[b,h,g,d] * W_out[h*64+d, c], stored transposed bf16 hi/lo
__global__ void k_P(const float* __restrict__ Wout) {
    int bh = blockIdx.x, b = bh >> 3, h = bh & 7;
    int col0 = blockIdx.y * 64;
    __shared__ float s_a[64][65];
    __shared__ float s_b[64][64];
    int t = threadIdx.x;
    for (int i = t; i < 4096; i += 256) {
        int r = i >> 6, c = i & 63;
        s_a[r][c] = g_outtok[(size_t)bh * 4096 + i];
        s_b[r][c] = Wout[(size_t)(h * 64 + r) * DM + col0 + c];
    }
    __syncthreads();
    int tx = t & 15, ty = t >> 4;
    float acc[4][4] = {};
    for (int d = 0; d < 64; d++) {
        float av[4], bv[4];
#pragma unroll
        for (int i = 0; i < 4; i++) av[i] = s_a[ty * 4 + i][d];
#pragma unroll
        for (int j = 0; j < 4; j++) bv[j] = s_b[d][tx * 4 + j];
#pragma unroll
        for (int i = 0; i < 4; i++)
#pragma unroll
            for (int j = 0; j < 4; j++) acc[i][j] = fmaf(av[i], bv[j], acc[i][j]);
    }
#pragma unroll
    for (int i = 0; i < 4; i++)
#pragma unroll
        for (int j = 0; j < 4; j++) {
            int r = h * 64 + ty * 4 + i;       // k index of P
            int c = col0 + tx * 4 + j;         // output col
            __nv_bfloat16 hh, ll;
            bsplit(acc[i][j], hh, ll);
            g_Pthi[((size_t)b * DM + c) * DM + r] = hh;
            g_Ptlo[((size_t)b * DM + c) * DM + r] = ll;
        }
}

// out[n, :] = w[n, :] @ P[batch(n)] via mma.sync bf16x3, gathered rows, 3-stage pipeline
__global__ void __launch_bounds__(256, 2)
k_final_mma(float* __restrict__ out) {
    int b = blockIdx.z;
    int cnt = g_rowcnt[b];
    int r0 = blockIdx.y * 128;
    if (r0 >= cnt) return;
    int nr = cnt - r0; if (nr > 128) nr = 128;
    extern __shared__ char dynsmem[];
    uint32_t sb = smem_to_u32(dynsmem);
    __shared__ int rid[128];
    int t = threadIdx.x;
    int lane = t & 31, wid = t >> 5;
    int wm = (wid & 3) * 32, wn = (wid >> 2) * 64;
    int col0 = blockIdx.x * 128;
    int start = g_rowstart[b];
    if (t < 128) rid[t] = g_rowlist[start + r0 + (t < nr ? t : nr - 1)];
    __syncthreads();
    float acc[2][8][4] = {};
    int a_row = wm + (lane & 15);
    int a_u = lane >> 4;
    int b_row = wn + (lane & 7) + ((lane >> 4) << 3);
    int b_u = (lane >> 3) & 1;
    const __nv_bfloat16* Ph = g_Pthi + ((size_t)b * DM + col0) * DM;
    const __nv_bfloat16* Pl = g_Ptlo + ((size_t)b * DM + col0) * DM;

    auto load_slab = [&](int kc, int stg) {
        uint32_t sbase = sb + stg * STG_BYTES;
#pragma unroll
        for (int half = 0; half < 2; half++) {
            int idx = half * 256 + t;
            int r = idx >> 2, c = idx & 3;
            uint32_t o = SW64_((uint32_t)(r * 64 + c * 16));
            size_t offa = (size_t)rid[r] * DM + kc + c * 8;
            size_t offb = (size_t)r * DM + kc + c * 8;
            cp16(sbase + OFFS_AH + o, g_whi + offa);
            cp16(sbase + OFFS_AL + o, g_wlo + offa);
            cp16(sbase + OFFS_BH + o, Ph + offb);
            cp16(sbase + OFFS_BL + o, Pl + offb);
        }
        CP_COMMIT();
    };

    load_slab(0, 0);
    load_slab(KSLAB, 1);
#pragma unroll 1
    for (int ch = 0; ch < NSLAB; ch++) {
        if (ch + 2 < NSLAB) { load_slab((ch + 2) * KSLAB, (ch + 2) % 3); CP_WAIT2(); }
        else if (ch + 1 < NSLAB) { CP_WAIT1(); }
        else { CP_WAIT0(); }
        __syncthreads();
        uint32_t sbase = sb + (ch % 3) * STG_BYTES;
#pragma unroll
        for (int ks = 0; ks < 2; ks++) {
            uint32_t ah[2][4], al[2][4];
#pragma unroll
            for (int mt = 0; mt < 2; mt++) {
                uint32_t off = SW64_((uint32_t)((a_row + mt * 16) * 64 + ks * 32 + a_u * 16));
                ldsm4(ah[mt], sbase + OFFS_AH + off);
                ldsm4(al[mt], sbase + OFFS_AL + off);
            }
#pragma unroll
            for (int np = 0; np < 4; np++) {
                uint32_t bh[4], bl[4];
                uint32_t boff = SW64_((uint32_t)((b_row + np * 16) * 64 + ks * 32 + b_u * 16));
                ldsm4(bh, sbase + OFFS_BH + boff);
                ldsm4(bl, sbase + OFFS_BL + boff);
#pragma unroll
                for (int mt = 0; mt < 2; mt++) {
                    mma16816(acc[mt][np * 2 + 0], ah[mt], bh[0], bh[1]);
                    mma16816(acc[mt][np * 2 + 0], ah[mt], bl[0], bl[1]);
                    mma16816(acc[mt][np * 2 + 0], al[mt], bh[0], bh[1]);
                    mma16816(acc[mt][np * 2 + 1], ah[mt], bh[2], bh[3]);
                    mma16816(acc[mt][np * 2 + 1], ah[mt], bl[2], bl[3]);
                    mma16816(acc[mt][np * 2 + 1], al[mt], bh[2], bh[3]);
                }
            }
        }
        __syncthreads();
    }
    int g = lane >> 2, tig = lane & 3;
#pragma unroll
    for (int mt = 0; mt < 2; mt++)
#pragma unroll
        for (int nt = 0; nt < 8; nt++) {
            int ml = wm + mt * 16 + g;
            int c = col0 + wn + nt * 8 + tig * 2;
            if (ml < nr)
                *(float2*)(out + (size_t)rid[ml] * DM + c) =
                    make_float2(acc[mt][nt][0], acc[mt][nt][1]);
            if (ml + 8 < nr)
                *(float2*)(out + (size_t)rid[ml + 8] * DM + c) =
                    make_float2(acc[mt][nt][2], acc[mt][nt][3]);
        }
}

extern "C" void kernel_launch(void* const* d_in, const int* in_sizes, int n_in,
                              void* d_out, int out_size) {
    const float* x    = (const float*)d_in[0];
    const int*   bi   = (const int*)d_in[1];
    const float* son  = (const float*)d_in[2];
    const int*   sbi  = (const int*)d_in[3];
    const float* temp = (const float*)d_in[4];
    const float* Wfx  = (const float*)d_in[5];
    const float* bfx  = (const float*)d_in[6];
    const float* Wx   = (const float*)d_in[7];
    const float* bx   = (const float*)d_in[8];
    const float* Wsl  = (const float*)d_in[9];
    const float* bsl  = (const float*)d_in[10];
    const float* Wq   = (const float*)d_in[11];
    const float* bq   = (const float*)d_in[12];
    const float* Wk   = (const float*)d_in[13];
    const float* bk   = (const float*)d_in[14];
    const float* Wv   = (const float*)d_in[15];
    const float* bv   = (const float*)d_in[16];
    const float* Wck  = (const float*)d_in[17];
    const float* bck  = (const float*)d_in[18];
    const float* Wcv  = (const float*)d_in[19];
    const float* bcv  = (const float*)d_in[20];
    const float* Wout = (const float*)d_in[21];
    float* out = (float*)d_out;

    static cudaStream_t s1 = nullptr, s2 = nullptr;
    static cudaEvent_t eF = nullptr, e1 = nullptr, e2a = nullptr, e2b = nullptr;
    if (s1 == nullptr) {
        cudaStreamCreateWithFlags(&s1, cudaStreamNonBlocking);
        cudaStreamCreateWithFlags(&s2, cudaStreamNonBlocking);
        cudaEventCreateWithFlags(&eF, cudaEventDisableTiming);
        cudaEventCreateWithFlags(&e1, cudaEventDisableTiming);
        cudaEventCreateWithFlags(&e2a, cudaEventDisableTiming);
        cudaEventCreateWithFlags(&e2b, cudaEventDisableTiming);
        cudaFuncSetAttribute(k_gemm_mma, cudaFuncAttributeMaxDynamicSharedMemorySize, SMEM_MMA);
        cudaFuncSetAttribute(k_final_mma, cudaFuncAttributeMaxDynamicSharedMemorySize, SMEM_MMA);
        cudaFuncSetAttribute(k_qkvattn, cudaFuncAttributeMaxDynamicSharedMemorySize, QKV_SMEM);
    }

    // fork
    cudaEventRecord(eF, 0);
    cudaStreamWaitEvent(s1, eF, 0);
    cudaStreamWaitEvent(s2, eF, 0);

    // stream s1: batch bucketing chain (independent of x path)
    k_zero<<<1024, 256, 0, s1>>>();
    k_count<<<80, 256, 0, s1>>>(bi, sbi);
    k_prefix<<<1, 1, 0, s1>>>();
    k_scatter<<<80, 256, 0, s1>>>(bi, sbi);
    cudaEventRecord(e1, s1);

    // stream s2: bias fold + weight transpose (feed gemm), then sonata K/V projection
    k_bcomb<<<1, 512, 0, s2>>>(bx, Wsl, bsl);
    k_wcomb<<<dim3(512, 2), 256, 0, s2>>>(Wx, Wsl, Wfx);
    cudaEventRecord(e2a, s2);
    k_skv<<<dim3(512, 2), 256, 0, s2>>>(son, Wck, bck, Wcv, bcv);
    cudaEventRecord(e2b, s2);

    // main stream
    k_cvt_x<<<8192, 256>>>(x);
    cudaStreamWaitEvent(0, e2a, 0);
    k_gemm_mma<<<dim3(8, 128), 256, SMEM_MMA>>>(bfx, temp);
    cudaStreamWaitEvent(0, e1, 0);
    k_tokens<<<dim3(64, 32), 256>>>();
    k_qkvattn<<<64, 256, QKV_SMEM>>>(Wq, bq, Wk, bk, Wv, bv);
    cudaStreamWaitEvent(0, e2b, 0);
    k_cross_score<<<dim3(64, 8), 256>>>();
    k_cross_out<<<dim3(64, 8), 256>>>();
    k_P<<<dim3(64, 8), 256>>>(Wout);
    k_final_mma<<<dim3(4, 128, 8), 256, SMEM_MMA>>>(out);
}